// round 13
// baseline (speedup 1.0000x reference)
#include <cuda_runtime.h>
#include <math.h>

// Problem constants (from reference): B=2,000,000 time steps, SEQ=1, IN=2
#define SPIN 365
#define TRAIN 1000000

// Chunked-scan: each lane owns CHUNK steps, warming up WARM steps from c=0.
// WARM=128 measured at rel_err 8.6e-7 (R12) — huge margin vs 1e-3 tolerance.
#define CHUNK 64
#define WARM 128
#define THREADS 128                // lanes per block (4 warps)
#define BT (THREADS * CHUNK)       // 8192 contiguous t per block

// smem: (BT+WARM) steps x 2 words (u1|c, u2) + 2-word skew per 64-step segment
#define SMEM_STEPS (BT + WARM)                         // 8320
#define SMEM_WORDS (2 * SMEM_STEPS + 2 * (SMEM_STEPS / 64))   // 16900
#define SMEM_BYTES (SMEM_WORDS * 4)                    // 67600 -> >=2 blocks/SM

#define F4_BASE  (368 / 4)         // y float4 region covers [368, 1000000)
#define F4_COUNT ((TRAIN - 368) / 4)

__device__ float g_part[2 * 512];
__device__ int   g_count;
__device__ int   g_flag;
__device__ float g_std;

// Reset the cross-block coordination state each replay (graph determinism).
__global__ void reset_kernel() { g_count = 0; g_flag = 0; }

// ---------------------------------------------------------------------------
// Fused single kernel:
//  0) cooperative coalesced load of x[base-WARM, base+BT) into skewed smem,
//     PLUS per-block partial reduction of a y slice (sum, sumsq) -> g_part.
//     Last block to arrive (g_count) finalizes std -> g_std, sets g_flag.
//  1) per-lane serial scan via LDS; pre-update c overwrites the u1 slot.
//     sigmoid via MUFU.TANH: c' = (base - P*c) - (P*c)*tanh(h), P=oo1/2,
//     h=(A+c*S)/2. Critical path FFMA(4)->TANH(16)->FFMA(4) = 24 cyc/step.
//  2) spin (near-zero wait: ~6us of phase 0+1 >> ~2us reduce) on g_flag,
//     then block-coalesced gate recompute + STG.128 __stcs streaming stores.
// Deadlock-free: 67.6KB smem => >=2 blocks/SM => 296 >= 245 blocks all
// resident in wave 1, and every block writes its partial before any spin.
// ---------------------------------------------------------------------------

#define PHYS(idx) (2 * (idx) + (((idx) >> 6) << 1))

#define STEP(U1, U2)                                                         \
    {                                                                        \
        float h_  = fmaf(c, Sh, Ah);                                         \
        float th_; asm("tanh.approx.f32 %0, %1;" : "=f"(th_) : "f"(h_));     \
        float base_ = (c + (U1)) - fminf(ol1 * c, (U2));                     \
        float k2_ = fmaf(-P, c, base_);                                      \
        float Pc_ = P * c;                                                   \
        c = fmaf(-Pc_, th_, k2_);                                            \
    }

__global__ void __launch_bounds__(THREADS)
fused_kernel(const float* __restrict__ x, const int* __restrict__ tlp,
             const float* __restrict__ y,
             const float* __restrict__ cm,  const float* __restrict__ cs,
             const float* __restrict__ wom, const float* __restrict__ wlm,
             const float* __restrict__ wfm, const float* __restrict__ b0p,
             const float* __restrict__ wb1p,
             float* __restrict__ out, int B, int ychunk) {
    extern __shared__ float sx[];                  // SMEM_WORDS floats
    __shared__ float yred[2][THREADS / 32];
    __shared__ int   is_last;

    int tid = threadIdx.x;
    int blockBase = blockIdx.x * BT;
    int tl = *tlp;

    float eo  = __expf(*wom), el = __expf(*wlm), ef = __expf(*wfm);
    float den = eo + el + ef;
    float oo1 = eo / den, ol1 = el / den;
    float S = (*wb1p) / (*cs);
    float A = (*b0p) - (*cm) * S;
    float Sh = 0.5f * S, Ah = 0.5f * A;            // h = (A + c*S)/2
    float P  = 0.5f * oo1;

    const float4* __restrict__ x4 = (const float4*)x;
    const float4* __restrict__ y4 = (const float4*)y;
    const int tlo0 = blockBase - WARM;             // idx = t - tlo0

    // ---------------- Phase 0a: y partial reduction (this block's slice) ---
    {
        float s = 0.f, s2 = 0.f;
        int y0 = blockIdx.x * ychunk;
#pragma unroll 4
        for (int j = tid; j < ychunk; j += THREADS) {
            int i = y0 + j;
            if (i < F4_COUNT) {
                float4 v = __ldcs(&y4[F4_BASE + i]);
                s  += (v.x + v.y) + (v.z + v.w);
                s2 += (v.x * v.x + v.y * v.y) + (v.z * v.z + v.w * v.w);
            }
        }
        if (blockIdx.x == 0 && tid == 0) {         // scalar head 365..367
            for (int i = SPIN; i < 368; ++i) { float v = __ldcs(&y[i]); s += v; s2 += v * v; }
        }
#pragma unroll
        for (int o = 16; o > 0; o >>= 1) {
            s  += __shfl_down_sync(0xffffffffu, s, o);
            s2 += __shfl_down_sync(0xffffffffu, s2, o);
        }
        int w = tid >> 5, l = tid & 31;
        if (l == 0) { yred[0][w] = s; yred[1][w] = s2; }
    }

    // ---------------- Phase 0b: cooperative coalesced x load ---------------
    {
        int lo = max(0, tlo0);                     // even (blockBase, WARM even)
        int hi = min(B, blockBase + BT);           // even (B even)
        int nf4 = (hi - lo) >> 1;                  // float4 = 2 steps
        int g0  = lo >> 1;
        for (int j = tid; j < nf4; j += THREADS) {
            float4 u = __ldcs(&x4[g0 + j]);
            int idx = (lo + 2 * j) - tlo0;         // even; pair stays in segment
            int p = PHYS(idx);
            *(float2*)&sx[p]     = make_float2(u.x, u.y);
            *(float2*)&sx[p + 2] = make_float2(u.z, u.w);
        }
    }
    __syncthreads();

    // ---------------- Phase 0c: publish partial; last block finalizes ------
    if (tid == 0) {
        float ts = 0.f, t2 = 0.f;
#pragma unroll
        for (int i = 0; i < THREADS / 32; i++) { ts += yred[0][i]; t2 += yred[1][i]; }
        g_part[2 * blockIdx.x]     = ts;
        g_part[2 * blockIdx.x + 1] = t2;
        __threadfence();
        int old = atomicAdd(&g_count, 1);
        is_last = (old == (int)gridDim.x - 1) ? 1 : 0;
    }
    __syncthreads();
    if (is_last && tid < 32) {                     // finalize in one warp
        float s = 0.f, s2 = 0.f;
        int nb = gridDim.x;
        for (int i = tid; i < nb; i += 32) {
            s  += g_part[2 * i];
            s2 += g_part[2 * i + 1];
        }
#pragma unroll
        for (int o = 16; o > 0; o >>= 1) {
            s  += __shfl_down_sync(0xffffffffu, s, o);
            s2 += __shfl_down_sync(0xffffffffu, s2, o);
        }
        if (tid == 0) {
            double n  = (double)(TRAIN - SPIN);
            double ds = (double)s, d2 = (double)s2;
            double var = (d2 - ds * ds / n) / (n - 1.0);
            g_std = (float)sqrt(var > 0.0 ? var : 0.0);
            __threadfence();
            atomicExch(&g_flag, 1);
        }
    }

    // ---------------- Phase 1: serial scan via LDS -------------------------
    {
        int start = blockBase + tid * CHUNK;
        if (start < B) {
            int end = min(start + CHUNK, B);
            int s0  = max(start, tl);
            if (s0 < end) {
                int t0 = max(tl, start - WARM);    // == tl => exact init
                float c = 0.0f;
                int t = t0;
#pragma unroll 4
                for (; t < s0; ++t) {              // warm-up: no writes
                    int idx = t - tlo0;
                    float2 u = *(float2*)&sx[PHYS(idx)];
                    STEP(u.x, u.y);
                }
#pragma unroll 4
                for (; t < end; ++t) {             // owned: stash pre-update c
                    int idx = t - tlo0;
                    int p = PHYS(idx);
                    float2 u = *(float2*)&sx[p];
                    sx[p] = c;                     // overwrite u1 slot with c
                    STEP(u.x, u.y);
                }
            }
        }
    }
    // ---------------- std handshake (near-zero wait) -----------------------
    if (tid == 0) {
        while (atomicAdd(&g_flag, 0) == 0) { }
        __threadfence();
    }
    __syncthreads();
    float stdv = *((volatile float*)&g_std);

    // ---------------- Phase 2: coalesced gate recompute + stores -----------
    // Output = concat: [h_n | c_n | l_n | lc_n | bp_n(0) | Gate_ib(0) |
    //   Gate_oo | Gate_ol | Gate_olc | Gate_f | h_nout(B,2) | obs_std]
    size_t Bz = (size_t)B;
    float* h_n  = out;
    float* c_n  = out + Bz;
    float* l_n  = out + 2 * Bz;
    float* lc_n = out + 3 * Bz;
    float* z1   = out + 4 * Bz;
    float* z2   = out + 5 * Bz;
    float* goo  = out + 6 * Bz;
    float* gol  = out + 7 * Bz;
    float* golc = out + 8 * Bz;
    float* gf   = out + 9 * Bz;
    float* hout = out + 10 * Bz;
    float* ostd = out + 12 * Bz;

    int tmax = min(BT, B - blockBase);             // multiple of 4 (B%4==0)

    for (int lt = tid * 4; lt < tmax; lt += THREADS * 4) {
        int t = blockBase + lt;
        int idx = lt + WARM;                       // owned region starts at WARM
        int p = PHYS(idx);                         // group of 4 stays in segment
        float2 a0 = *(float2*)&sx[p];              // (c, u2) for t
        float2 a1 = *(float2*)&sx[p + 2];
        float2 a2 = *(float2*)&sx[p + 4];
        float2 a3 = *(float2*)&sx[p + 6];
        float cvw[4] = {a0.x, a1.x, a2.x, a3.x};
        float u2v[4] = {a0.y, a1.y, a2.y, a3.y};

        float qv[4], cv[4], lv[4], lcv[4], oov[4], olcv[4], gfv[4], olv[4], sdv[4];
#pragma unroll
        for (int j = 0; j < 4; ++j) {
            bool valid = (t + j) >= tl;
            float c  = cvw[j];
            float u2 = u2v[j];
            float h  = fmaf(c, Sh, Ah);
            float th; asm("tanh.approx.f32 %0, %1;" : "=f"(th) : "f"(h));
            float oo = fmaf(P, th, P);             // oo1 * sigmoid
            float rc; asm("rcp.approx.f32 %0, %1;" : "=f"(rc) : "f"(c));
            float olc = (c > 0.0f) ? fminf(ol1, u2 * rc) : ol1;
            float q  = oo * c;
            float lc = fminf(ol1 * c, u2);         // == olc*c for c>=0, u2>=0
            qv[j]   = valid ? q : 0.f;
            cv[j]   = valid ? c : 0.f;
            lv[j]   = valid ? ol1 * c : 0.f;
            lcv[j]  = valid ? lc : 0.f;
            oov[j]  = valid ? oo : 0.f;
            olv[j]  = valid ? ol1 : 0.f;
            olcv[j] = valid ? olc : 0.f;
            gfv[j]  = valid ? (1.0f - oo - olc) : 0.f;
            sdv[j]  = valid ? stdv : 0.f;
        }
        const float4 zero4 = make_float4(0.f, 0.f, 0.f, 0.f);
        __stcs((float4*)(h_n  + t), make_float4(qv[0], qv[1], qv[2], qv[3]));
        __stcs((float4*)(c_n  + t), make_float4(cv[0], cv[1], cv[2], cv[3]));
        __stcs((float4*)(l_n  + t), make_float4(lv[0], lv[1], lv[2], lv[3]));
        __stcs((float4*)(lc_n + t), make_float4(lcv[0], lcv[1], lcv[2], lcv[3]));
        __stcs((float4*)(z1   + t), zero4);
        __stcs((float4*)(z2   + t), zero4);
        __stcs((float4*)(goo  + t), make_float4(oov[0], oov[1], oov[2], oov[3]));
        __stcs((float4*)(gol  + t), make_float4(olv[0], olv[1], olv[2], olv[3]));
        __stcs((float4*)(golc + t), make_float4(olcv[0], olcv[1], olcv[2], olcv[3]));
        __stcs((float4*)(gf   + t), make_float4(gfv[0], gfv[1], gfv[2], gfv[3]));
        __stcs((float4*)(hout + 2 * (size_t)t),     make_float4(qv[0], sdv[0], qv[1], sdv[1]));
        __stcs((float4*)(hout + 2 * (size_t)t + 4), make_float4(qv[2], sdv[2], qv[3], sdv[3]));
        __stcs((float4*)(ostd + t), make_float4(sdv[0], sdv[1], sdv[2], sdv[3]));
    }
}

// ---------------------------------------------------------------------------
// Inputs (metadata order): x, epoch, time_lag, y_obs, c_mean, c_std,
//   weight_r_yom, weight_r_ylm, weight_r_yfm, bias_b0_yom, weight_b1_yom
// ---------------------------------------------------------------------------
extern "C" void kernel_launch(void* const* d_in, const int* in_sizes, int n_in,
                              void* d_out, int out_size) {
    const float* x    = (const float*)d_in[0];
    const int*   tlp  = (const int*)d_in[2];
    const float* y    = (const float*)d_in[3];
    const float* cm   = (const float*)d_in[4];
    const float* cs   = (const float*)d_in[5];
    const float* wom  = (const float*)d_in[6];
    const float* wlm  = (const float*)d_in[7];
    const float* wfm  = (const float*)d_in[8];
    const float* b0p  = (const float*)d_in[9];
    const float* wb1p = (const float*)d_in[10];

    int B = in_sizes[0] / 2;   // x is [B, 1, 2]

    cudaFuncSetAttribute(fused_kernel, cudaFuncAttributeMaxDynamicSharedMemorySize,
                         SMEM_BYTES);

    int blocks = (B + BT - 1) / BT;                // 245 (all wave-1 resident)
    int ychunk = (F4_COUNT + blocks - 1) / blocks; // y float4s per block

    reset_kernel<<<1, 1>>>();
    fused_kernel<<<blocks, THREADS, SMEM_BYTES>>>(x, tlp, y, cm, cs, wom, wlm, wfm,
                                                  b0p, wb1p, (float*)d_out, B, ychunk);
}

// round 16
// speedup vs baseline: 1.0629x; 1.0629x over previous
#include <cuda_runtime.h>
#include <math.h>

// Problem constants (from reference): B=2,000,000 time steps, SEQ=1, IN=2
#define SPIN 365
#define TRAIN 1000000

// Chunked-scan: each lane owns CHUNK steps, warming up WARM steps from c=0.
// WARM=128 measured at rel_err 8.6e-7 (R12/R13) — huge margin vs 1e-3.
#define CHUNK 64
#define WARM 128
#define THREADS 128                // lanes per block (4 warps)
#define BT (THREADS * CHUNK)       // 8192 contiguous t per block

// SoA smem: cArr (u1 -> c -> q) and u2Arr, each padded 2 words per 64-step
// segment. phys(idx) = idx + 2*(idx>>6) is STRICTLY INCREASING => injective
// (the R15 bug was a wrapping, non-injective skew). Bank profile:
//   phase 1 (lane stride 64): (66t+k) mod 32 -> 2-way
//   phase 2 (thread stride 4): LDS.64 at 4t+const -> 2-way (was 4-way AoS)
// Pairs (idx even / 4-aligned groups) never straddle a 64-segment.
#define SMEM_STEPS (BT + WARM)                         // 8320
#define CU_WORDS  (SMEM_STEPS + 2 * (SMEM_STEPS / 64)) // 8580
#define SMEM_WORDS (2 * CU_WORDS)                      // 17160
#define SMEM_BYTES (SMEM_WORDS * 4)                    // 68640 -> 3 blocks/SM

#define PC(idx) ((idx) + 2 * ((idx) >> 6))
#define PU(idx) (CU_WORDS + PC(idx))

#define F4_BASE  (368 / 4)         // y float4 region covers [368, 1000000)
#define F4_COUNT ((TRAIN - 368) / 4)

__device__ float g_part[2 * 512];
__device__ int   g_count;
__device__ int   g_flag;
__device__ float g_std;

// Reset cross-block coordination state each replay (graph determinism).
__global__ void reset_kernel() { g_count = 0; g_flag = 0; }

// ---------------------------------------------------------------------------
// Single fused kernel:
//  0a) per-block partial y reduction (sum, sumsq) -> g_part (+count).
//  0b) cooperative coalesced x load into padded SoA smem.
//  1)  per-lane serial scan via LDS; pre-update c overwrites the u1 slot.
//      sigmoid via MUFU.TANH: c' = (base - P*c) - (P*c)*tanh(h), P=oo1/2.
//  2A) std-INDEPENDENT streams (10 of 13) stored; q stashed in dead c slot.
//  --  handshake on g_flag only now (hidden behind ~80% of store work).
//  2B) hout (q,std pairs) + ostd from stashed q.
// Deadlock-free: 68.6KB smem => 3 blocks/SM => 444 >= 245 blocks resident,
// and every block publishes its partial before any spin.
// ---------------------------------------------------------------------------

#define STEP(U1, U2)                                                         \
    {                                                                        \
        float h_  = fmaf(c, Sh, Ah);                                         \
        float th_; asm("tanh.approx.f32 %0, %1;" : "=f"(th_) : "f"(h_));     \
        float base_ = (c + (U1)) - fminf(ol1 * c, (U2));                     \
        float k2_ = fmaf(-P, c, base_);                                      \
        float Pc_ = P * c;                                                   \
        c = fmaf(-Pc_, th_, k2_);                                            \
    }

__global__ void __launch_bounds__(THREADS)
fused_kernel(const float* __restrict__ x, const int* __restrict__ tlp,
             const float* __restrict__ y,
             const float* __restrict__ cm,  const float* __restrict__ cs,
             const float* __restrict__ wom, const float* __restrict__ wlm,
             const float* __restrict__ wfm, const float* __restrict__ b0p,
             const float* __restrict__ wb1p,
             float* __restrict__ out, int B, int ychunk) {
    extern __shared__ float sx[];                  // SMEM_WORDS floats
    __shared__ float yred[2][THREADS / 32];
    __shared__ int   is_last;

    int tid = threadIdx.x;
    int blockBase = blockIdx.x * BT;
    int tl = *tlp;

    float eo  = __expf(*wom), el = __expf(*wlm), ef = __expf(*wfm);
    float den = eo + el + ef;
    float oo1 = eo / den, ol1 = el / den;
    float S = (*wb1p) / (*cs);
    float A = (*b0p) - (*cm) * S;
    float Sh = 0.5f * S, Ah = 0.5f * A;            // h = (A + c*S)/2
    float P  = 0.5f * oo1;

    const float4* __restrict__ x4 = (const float4*)x;
    const float4* __restrict__ y4 = (const float4*)y;
    const int tlo0 = blockBase - WARM;             // idx = t - tlo0

    // ---------------- Phase 0a: y partial reduction ------------------------
    {
        float s = 0.f, s2 = 0.f;
        int y0 = blockIdx.x * ychunk;
#pragma unroll 4
        for (int j = tid; j < ychunk; j += THREADS) {
            int i = y0 + j;
            if (i < F4_COUNT) {
                float4 v = __ldcs(&y4[F4_BASE + i]);
                s  += (v.x + v.y) + (v.z + v.w);
                s2 += (v.x * v.x + v.y * v.y) + (v.z * v.z + v.w * v.w);
            }
        }
        if (blockIdx.x == 0 && tid == 0) {         // scalar head 365..367
            for (int i = SPIN; i < 368; ++i) { float v = __ldcs(&y[i]); s += v; s2 += v * v; }
        }
#pragma unroll
        for (int o = 16; o > 0; o >>= 1) {
            s  += __shfl_down_sync(0xffffffffu, s, o);
            s2 += __shfl_down_sync(0xffffffffu, s2, o);
        }
        int w = tid >> 5, l = tid & 31;
        if (l == 0) { yred[0][w] = s; yred[1][w] = s2; }
    }

    // ---------------- Phase 0b: cooperative coalesced x load (SoA) ---------
    {
        int lo = max(0, tlo0);                     // even (blockBase, WARM even)
        int hi = min(B, blockBase + BT);           // even (B even)
        int nf4 = (hi - lo) >> 1;                  // float4 = 2 steps
        int g0  = lo >> 1;
        for (int j = tid; j < nf4; j += THREADS) {
            float4 u = __ldcs(&x4[g0 + j]);
            int idx = (lo + 2 * j) - tlo0;         // even; pair in one segment
            int pc = PC(idx);
            *(float2*)&sx[pc]           = make_float2(u.x, u.z);  // u1 pair
            *(float2*)&sx[CU_WORDS + pc] = make_float2(u.y, u.w); // u2 pair
        }
    }
    __syncthreads();

    // ---------------- Phase 0c: publish partial; last block finalizes ------
    if (tid == 0) {
        float ts = 0.f, t2 = 0.f;
#pragma unroll
        for (int i = 0; i < THREADS / 32; i++) { ts += yred[0][i]; t2 += yred[1][i]; }
        g_part[2 * blockIdx.x]     = ts;
        g_part[2 * blockIdx.x + 1] = t2;
        __threadfence();
        int old = atomicAdd(&g_count, 1);
        is_last = (old == (int)gridDim.x - 1) ? 1 : 0;
    }
    __syncthreads();
    if (is_last && tid < 32) {                     // finalize in one warp
        float s = 0.f, s2 = 0.f;
        int nb = gridDim.x;
        for (int i = tid; i < nb; i += 32) {
            s  += g_part[2 * i];
            s2 += g_part[2 * i + 1];
        }
#pragma unroll
        for (int o = 16; o > 0; o >>= 1) {
            s  += __shfl_down_sync(0xffffffffu, s, o);
            s2 += __shfl_down_sync(0xffffffffu, s2, o);
        }
        if (tid == 0) {
            double n  = (double)(TRAIN - SPIN);
            double ds = (double)s, d2 = (double)s2;
            double var = (d2 - ds * ds / n) / (n - 1.0);
            g_std = (float)sqrt(var > 0.0 ? var : 0.0);
            __threadfence();
            atomicExch(&g_flag, 1);
        }
    }

    // ---------------- Phase 1: serial scan via LDS -------------------------
    {
        int start = blockBase + tid * CHUNK;
        if (start < B) {
            int end = min(start + CHUNK, B);
            int s0  = max(start, tl);
            if (s0 < end) {
                int t0 = max(tl, start - WARM);    // == tl => exact init
                float c = 0.0f;
                int t = t0;
#pragma unroll 4
                for (; t < s0; ++t) {              // warm-up: no writes
                    int idx = t - tlo0;
                    int pc = PC(idx);
                    float u1 = sx[pc];
                    float u2 = sx[CU_WORDS + pc];
                    STEP(u1, u2);
                }
#pragma unroll 4
                for (; t < end; ++t) {             // owned: stash pre-update c
                    int idx = t - tlo0;
                    int pc = PC(idx);
                    float u1 = sx[pc];
                    float u2 = sx[CU_WORDS + pc];
                    sx[pc] = c;                    // overwrite u1 slot with c
                    STEP(u1, u2);
                }
            }
        }
    }
    __syncthreads();

    // ---------------- Phase 2A: std-independent streams --------------------
    // Output = concat: [h_n | c_n | l_n | lc_n | bp_n(0) | Gate_ib(0) |
    //   Gate_oo | Gate_ol | Gate_olc | Gate_f | h_nout(B,2) | obs_std]
    size_t Bz = (size_t)B;
    float* h_n  = out;
    float* c_n  = out + Bz;
    float* l_n  = out + 2 * Bz;
    float* lc_n = out + 3 * Bz;
    float* z1   = out + 4 * Bz;
    float* z2   = out + 5 * Bz;
    float* goo  = out + 6 * Bz;
    float* gol  = out + 7 * Bz;
    float* golc = out + 8 * Bz;
    float* gf   = out + 9 * Bz;
    float* hout = out + 10 * Bz;
    float* ostd = out + 12 * Bz;

    int tmax = min(BT, B - blockBase);             // multiple of 4 (B%4==0)

    for (int lt = tid * 4; lt < tmax; lt += THREADS * 4) {
        int t = blockBase + lt;
        int idx = lt + WARM;                       // 4-aligned, one segment
        int pc = PC(idx);
        int pu = CU_WORDS + pc;
        float2 ca = *(float2*)&sx[pc];             // c for t, t+1
        float2 cb = *(float2*)&sx[pc + 2];         // c for t+2, t+3
        float2 ua = *(float2*)&sx[pu];             // u2 for t, t+1
        float2 ub = *(float2*)&sx[pu + 2];
        float cvw[4] = {ca.x, ca.y, cb.x, cb.y};
        float u2v[4] = {ua.x, ua.y, ub.x, ub.y};

        float qv[4], cv[4], lv[4], lcv[4], oov[4], olcv[4], gfv[4], olv[4];
#pragma unroll
        for (int j = 0; j < 4; ++j) {
            bool valid = (t + j) >= tl;
            float c  = cvw[j];
            float u2 = u2v[j];
            float h  = fmaf(c, Sh, Ah);
            float th; asm("tanh.approx.f32 %0, %1;" : "=f"(th) : "f"(h));
            float oo = fmaf(P, th, P);             // oo1 * sigmoid
            float rc; asm("rcp.approx.f32 %0, %1;" : "=f"(rc) : "f"(c));
            float olc = (c > 0.0f) ? fminf(ol1, u2 * rc) : ol1;
            float q  = oo * c;
            float lc = fminf(ol1 * c, u2);         // == olc*c for c>=0, u2>=0
            qv[j]   = valid ? q : 0.f;
            cv[j]   = valid ? c : 0.f;
            lv[j]   = valid ? ol1 * c : 0.f;
            lcv[j]  = valid ? lc : 0.f;
            oov[j]  = valid ? oo : 0.f;
            olv[j]  = valid ? ol1 : 0.f;
            olcv[j] = valid ? olc : 0.f;
            gfv[j]  = valid ? (1.0f - oo - olc) : 0.f;
            sx[pc + j] = qv[j];                    // stash q (c slot is dead)
        }
        const float4 zero4 = make_float4(0.f, 0.f, 0.f, 0.f);
        __stcs((float4*)(h_n  + t), make_float4(qv[0], qv[1], qv[2], qv[3]));
        __stcs((float4*)(c_n  + t), make_float4(cv[0], cv[1], cv[2], cv[3]));
        __stcs((float4*)(l_n  + t), make_float4(lv[0], lv[1], lv[2], lv[3]));
        __stcs((float4*)(lc_n + t), make_float4(lcv[0], lcv[1], lcv[2], lcv[3]));
        __stcs((float4*)(z1   + t), zero4);
        __stcs((float4*)(z2   + t), zero4);
        __stcs((float4*)(goo  + t), make_float4(oov[0], oov[1], oov[2], oov[3]));
        __stcs((float4*)(gol  + t), make_float4(olv[0], olv[1], olv[2], olv[3]));
        __stcs((float4*)(golc + t), make_float4(olcv[0], olcv[1], olcv[2], olcv[3]));
        __stcs((float4*)(gf   + t), make_float4(gfv[0], gfv[1], gfv[2], gfv[3]));
    }

    // ---------------- std handshake (hidden behind phase 2A) ---------------
    if (tid == 0) {
        while (atomicAdd(&g_flag, 0) == 0) { }
        __threadfence();
    }
    __syncthreads();
    float stdv = *((volatile float*)&g_std);

    // ---------------- Phase 2B: hout + ostd from stashed q -----------------
    for (int lt = tid * 4; lt < tmax; lt += THREADS * 4) {
        int t = blockBase + lt;
        int idx = lt + WARM;
        int pc = PC(idx);
        float q0 = sx[pc],     q1 = sx[pc + 1];
        float q2 = sx[pc + 2], q3 = sx[pc + 3];
        float s0 = (t     >= tl) ? stdv : 0.f;
        float s1 = (t + 1 >= tl) ? stdv : 0.f;
        float s2 = (t + 2 >= tl) ? stdv : 0.f;
        float s3 = (t + 3 >= tl) ? stdv : 0.f;
        __stcs((float4*)(hout + 2 * (size_t)t),     make_float4(q0, s0, q1, s1));
        __stcs((float4*)(hout + 2 * (size_t)t + 4), make_float4(q2, s2, q3, s3));
        __stcs((float4*)(ostd + t), make_float4(s0, s1, s2, s3));
    }
}

// ---------------------------------------------------------------------------
// Inputs (metadata order): x, epoch, time_lag, y_obs, c_mean, c_std,
//   weight_r_yom, weight_r_ylm, weight_r_yfm, bias_b0_yom, weight_b1_yom
// ---------------------------------------------------------------------------
extern "C" void kernel_launch(void* const* d_in, const int* in_sizes, int n_in,
                              void* d_out, int out_size) {
    const float* x    = (const float*)d_in[0];
    const int*   tlp  = (const int*)d_in[2];
    const float* y    = (const float*)d_in[3];
    const float* cm   = (const float*)d_in[4];
    const float* cs   = (const float*)d_in[5];
    const float* wom  = (const float*)d_in[6];
    const float* wlm  = (const float*)d_in[7];
    const float* wfm  = (const float*)d_in[8];
    const float* b0p  = (const float*)d_in[9];
    const float* wb1p = (const float*)d_in[10];

    int B = in_sizes[0] / 2;   // x is [B, 1, 2]

    cudaFuncSetAttribute(fused_kernel, cudaFuncAttributeMaxDynamicSharedMemorySize,
                         SMEM_BYTES);

    int blocks = (B + BT - 1) / BT;                // 245 (all wave-1 resident)
    int ychunk = (F4_COUNT + blocks - 1) / blocks; // y float4s per block

    reset_kernel<<<1, 1>>>();
    fused_kernel<<<blocks, THREADS, SMEM_BYTES>>>(x, tlp, y, cm, cs, wom, wlm, wfm,
                                                  b0p, wb1p, (float*)d_out, B, ychunk);
}